// round 1
// baseline (speedup 1.0000x reference)
#include <cuda_runtime.h>
#include <stdint.h>

// Problem constants
#define BB 4
#define CC 8192
#define HH 32
#define WW 32
#define HW 1024                 // H*W
#define CHW (CC * HW)           // 8388608
#define NPIX 4096               // B*H*W
#define ROWS 128                // B*H
#define NCHUNK 16
#define CHUNK (CC / NCHUNK)     // 512
#define DD 256                  // embedding dim
#define QSIZE (BB * DD * HW)    // 1048576
#define OH_ELEMS ((size_t)BB * CC * HW)  // 33554432

// Scratch (static device globals — no allocation)
__device__ float g_mxg[NCHUNK][NPIX];
__device__ int   g_ixg[NCHUNK][NPIX];
__device__ float g_mx [NCHUNK][NPIX];
__device__ float g_s  [NCHUNK][NPIX];
__device__ float g_sx [NCHUNK][NPIX];
__device__ int   g_fidx[NPIX];

// ---------------------------------------------------------------------------
// Kernel 0: zero-fill the one_hot output region (float4, alignment-safe) and
// zero the kl scalar slot.
// ---------------------------------------------------------------------------
__global__ __launch_bounds__(256) void kzero(float* __restrict__ out,
                                             size_t kl_off, size_t oh_off) {
    if (blockIdx.x == 0 && threadIdx.x == 0) out[kl_off] = 0.0f;

    float* oh = out + oh_off;
    uintptr_t addr = (uintptr_t)oh;
    int head = (int)(((16u - (unsigned)(addr & 15u)) & 15u) >> 2);  // floats to 16B align
    size_t t = (size_t)blockIdx.x * blockDim.x + threadIdx.x;
    size_t nth = (size_t)gridDim.x * blockDim.x;

    if (t < (size_t)head) oh[t] = 0.0f;

    size_t n4 = (OH_ELEMS - head) >> 2;
    float4* o4 = (float4*)(oh + head);
    float4 z = make_float4(0.f, 0.f, 0.f, 0.f);
    for (size_t i = t; i < n4; i += nth) o4[i] = z;

    size_t tail0 = (size_t)head + (n4 << 2);
    size_t ntail = OH_ELEMS - tail0;
    if (t < ntail) oh[tail0 + t] = 0.0f;
}

// ---------------------------------------------------------------------------
// Kernel 1: per-pixel partial reductions over a channel chunk.
// Block = (chunk, row). 256 threads: warp w handles channels warp*4+csub (+k*32),
// lane = csub*8 + wg; wg selects a float4 group of 4 adjacent W pixels.
// Fully coalesced float4 loads of x and gumbel along W.
// ---------------------------------------------------------------------------
__global__ __launch_bounds__(256) void k1(const float* __restrict__ x,
                                          const float* __restrict__ g) {
    const int chunk = blockIdx.x;      // 0..15
    const int row   = blockIdx.y;      // 0..127 == b*32 + h
    const int b = row >> 5, h = row & 31;
    const int tid  = threadIdx.x;
    const int warp = tid >> 5, lane = tid & 31;
    const int csub = lane >> 3, wg = lane & 7;

    const size_t rowbase = (size_t)b * CHW + (size_t)h * WW + (size_t)wg * 4;
    const int c0 = chunk * CHUNK + warp * 4 + csub;

    float mxg[4], mx[4], s[4], sx[4];
    int ixg[4];
#pragma unroll
    for (int j = 0; j < 4; j++) {
        mxg[j] = -1e30f; ixg[j] = 0; mx[j] = -1e30f; s[j] = 0.f; sx[j] = 0.f;
    }

#pragma unroll 4
    for (int k = 0; k < CHUNK / 32; k++) {
        const int c = c0 + k * 32;
        const float4 xv = *(const float4*)(x + rowbase + (size_t)c * HW);
        const float4 gv = *(const float4*)(g + rowbase + (size_t)c * HW);
        const float xs[4] = {xv.x, xv.y, xv.z, xv.w};
        const float gs[4] = {gv.x, gv.y, gv.z, gv.w};
#pragma unroll
        for (int j = 0; j < 4; j++) {
            const float xx = xs[j];
            const float v = xx + gs[j];
            if (v > mxg[j]) { mxg[j] = v; ixg[j] = c; }   // ascending c: strict > keeps first
            sx[j] += xx;
            if (xx > mx[j]) { s[j] = s[j] * __expf(mx[j] - xx) + 1.0f; mx[j] = xx; }
            else            { s[j] += __expf(xx - mx[j]); }
        }
    }

    // Warp butterfly over csub (lanes differing in bits 3,4)
#pragma unroll
    for (int off = 8; off < 32; off <<= 1) {
#pragma unroll
        for (int j = 0; j < 4; j++) {
            float vm = __shfl_xor_sync(0xffffffffu, mxg[j], off);
            int   vi = __shfl_xor_sync(0xffffffffu, ixg[j], off);
            if (vm > mxg[j] || (vm == mxg[j] && vi < ixg[j])) { mxg[j] = vm; ixg[j] = vi; }
            float om = __shfl_xor_sync(0xffffffffu, mx[j], off);
            float os = __shfl_xor_sync(0xffffffffu, s[j],  off);
            float nm = fmaxf(mx[j], om);
            s[j] = s[j] * __expf(mx[j] - nm) + os * __expf(om - nm);
            mx[j] = nm;
            sx[j] += __shfl_xor_sync(0xffffffffu, sx[j], off);
        }
    }

    __shared__ float sh_mxg[8][8][4];
    __shared__ int   sh_ixg[8][8][4];
    __shared__ float sh_mx [8][8][4];
    __shared__ float sh_s  [8][8][4];
    __shared__ float sh_sx [8][8][4];

    if (csub == 0) {
#pragma unroll
        for (int j = 0; j < 4; j++) {
            sh_mxg[warp][wg][j] = mxg[j];
            sh_ixg[warp][wg][j] = ixg[j];
            sh_mx [warp][wg][j] = mx[j];
            sh_s  [warp][wg][j] = s[j];
            sh_sx [warp][wg][j] = sx[j];
        }
    }
    __syncthreads();

    if (tid < 32) {
        const int wg2 = tid >> 2, j = tid & 3;
        float M = -1e30f; int I = 0;
        float Mx = -1e30f, S = 0.f, SX = 0.f;
#pragma unroll
        for (int w = 0; w < 8; w++) {
            float vm = sh_mxg[w][wg2][j]; int vi = sh_ixg[w][wg2][j];
            if (vm > M || (vm == M && vi < I)) { M = vm; I = vi; }
            float om = sh_mx[w][wg2][j], os = sh_s[w][wg2][j];
            float nm = fmaxf(Mx, om);
            S = S * __expf(Mx - nm) + os * __expf(om - nm);
            Mx = nm;
            SX += sh_sx[w][wg2][j];
        }
        const int p = row * 32 + wg2 * 4 + j;   // b*1024 + h*32 + w
        g_mxg[chunk][p] = M;
        g_ixg[chunk][p] = I;
        g_mx [chunk][p] = Mx;
        g_s  [chunk][p] = S;
        g_sx [chunk][p] = SX;
    }
}

// ---------------------------------------------------------------------------
// Kernel 2: combine chunk partials, write one_hot '1's, store final idx,
// reduce KL and atomicAdd to the kl slot.
// ---------------------------------------------------------------------------
__global__ __launch_bounds__(256) void k2(float* __restrict__ out,
                                          size_t kl_off, size_t oh_off) {
    const int p = blockIdx.x * 256 + threadIdx.x;   // 16 blocks * 256 = 4096

    float M = -1e30f; int I = 0;
    float Mx = -1e30f, S = 0.f, SX = 0.f;
#pragma unroll
    for (int k = 0; k < NCHUNK; k++) {
        float vm = g_mxg[k][p]; int vi = g_ixg[k][p];
        if (vm > M || (vm == M && vi < I)) { M = vm; I = vi; }
        float om = g_mx[k][p], os = g_s[k][p];
        float nm = fmaxf(Mx, om);
        S = S * __expf(Mx - nm) + os * __expf(om - nm);
        Mx = nm;
        SX += g_sx[k][p];
    }

    g_fidx[p] = I;
    // one_hot[b, I, h, w] = 1
    const int b = p >> 10, hw = p & 1023;
    out[oh_off + (size_t)b * CHW + (size_t)I * HW + hw] = 1.0f;

    // KL per pixel: log(1/n) - mean(x) + lse(x)
    const float LOGT = -9.010913347279288f;        // -log(8192)
    float term = LOGT - SX * (1.0f / 8192.0f) + Mx + logf(S);

    __shared__ float red[256];
    red[threadIdx.x] = term;
    __syncthreads();
#pragma unroll
    for (int s2 = 128; s2 > 0; s2 >>= 1) {
        if (threadIdx.x < s2) red[threadIdx.x] += red[threadIdx.x + s2];
        __syncthreads();
    }
    if (threadIdx.x == 0) {
        // COMMITMENT_COST / B = 0.25 / 4
        atomicAdd(out + kl_off, red[0] * 0.0625f);
    }
}

// ---------------------------------------------------------------------------
// Kernel 3: quantized gather: out[b,d,h,w] = emb[idx[b,h,w]][d]
// ---------------------------------------------------------------------------
__global__ __launch_bounds__(256) void k3(const float* __restrict__ emb,
                                          float* __restrict__ out) {
    const int t = blockIdx.x * 256 + threadIdx.x;   // 4096 blocks * 256 = 1048576
    const int hw = t & 1023;
    const int d  = (t >> 10) & 255;
    const int b  = t >> 18;
    const int idx = g_fidx[b * 1024 + hw];
    out[t] = __ldg(emb + (size_t)idx * DD + d);
}

// ---------------------------------------------------------------------------
extern "C" void kernel_launch(void* const* d_in, const int* in_sizes, int n_in,
                              void* d_out, int out_size) {
    const float* x   = (const float*)d_in[0];
    const float* emb = (const float*)d_in[1];
    const float* gum = (const float*)d_in[2];
    float* out = (float*)d_out;

    // Output layout: [quantized (1048576)] [kl (1)] [one_hot (33554432)]
    const size_t oh_off = (size_t)out_size - OH_ELEMS;
    const size_t kl_off = oh_off - 1;

    kzero<<<8192, 256>>>(out, kl_off, oh_off);

    dim3 g1(NCHUNK, ROWS);
    k1<<<g1, 256>>>(x, gum);

    k2<<<NPIX / 256, 256>>>(out, kl_off, oh_off);

    k3<<<QSIZE / 256, 256>>>(emb, out);
}